// round 9
// baseline (speedup 1.0000x reference)
#include <cuda_runtime.h>

#define N_ 4
#define C_ 256
#define H_ 200
#define W_ 272
#define O_ 7
#define K_CH 10         // h-chunks
#define HCH 20          // H_ / K_CH

// Integral image, oct-blocked TRANSPOSED layout:
//   g_integ[(((n*H + h)*32 + co)*W + w)*8 + ci]   with co=c>>3, ci=c&7.
// Per (n,h,co) the 272*8 floats are CONTIGUOUS -> coalesced scan stores.
__device__ float g_integ[(size_t)N_ * H_ * W_ * C_];
// carry, same oct-blocked layout: [n][k][co][w][ci]
__device__ float g_carry[(size_t)N_ * K_CH * W_ * C_];

__device__ __forceinline__ float4 f4add(float4 a, float4 b) {
    return make_float4(a.x + b.x, a.y + b.y, a.z + b.z, a.w + b.w);
}
__device__ __forceinline__ float4 f4sub(float4 a, float4 b) {
    return make_float4(a.x - b.x, a.y - b.y, a.z - b.z, a.w - b.w);
}

// --------------------------------------------------------------------------
// Fused H-scan + W-scan + transpose. Block: 96 threads (3 warps),
// thread = 4 consecutive w (68 active). Block owns (n, h-chunk k, c-oct).
// Stores staged through bank-rotated smem -> fully coalesced STG.128.
// Grid: (32, 10, 4) = 1280 blocks.
// --------------------------------------------------------------------------
__global__ __launch_bounds__(96) void fused_scan(const float* __restrict__ fm) {
    __shared__ float  wsum[8][4];        // [channel][warp], 3 warps used
    __shared__ float4 xch[544];          // one h-row: 272 w * 8 c = 544 float4

    const int co = blockIdx.x;           // c-oct
    const int c0 = co * 8;
    const int k  = blockIdx.y;
    const int n  = blockIdx.z;
    const int slot = threadIdx.x;        // 0..95, active < 68
    const int lane = slot & 31;
    const int wid  = slot >> 5;          // 0..2
    const bool active = (slot < 68);

    float acc[8][4];
    #pragma unroll
    for (int j = 0; j < 8; ++j)
        #pragma unroll
        for (int e = 0; e < 4; ++e) acc[j][e] = 0.f;

    const float4* in0 = (const float4*)(fm + ((size_t)(n * C_ + c0) * H_
                          + (size_t)k * HCH) * W_) + (active ? slot : 0);
    // float4 base index of row (h = k*HCH), this co:
    float4* gout0 = (float4*)g_integ
        + ((size_t)((n * H_ + k * HCH) * 32 + co)) * (W_ * 2);

    for (int lh = 0; lh < HCH; ++lh) {
        float4 v[8];
        #pragma unroll
        for (int j = 0; j < 8; ++j)
            v[j] = in0[(size_t)j * (H_ * W_ / 4) + lh * (W_ / 4)];

        float sc[8][4];
        #pragma unroll
        for (int j = 0; j < 8; ++j) {
            if (!active) v[j] = make_float4(0.f, 0.f, 0.f, 0.f);
            acc[j][0] += v[j].x;
            acc[j][1] += v[j].y;
            acc[j][2] += v[j].z;
            acc[j][3] += v[j].w;
            const float i0 = acc[j][0];
            const float i1 = i0 + acc[j][1];
            const float i2 = i1 + acc[j][2];
            const float i3 = i2 + acc[j][3];
            float x = i3;                          // warp inclusive scan on totals
            #pragma unroll
            for (int d = 1; d < 32; d <<= 1) {
                float y = __shfl_up_sync(0xffffffff, x, d);
                if (lane >= d) x += y;
            }
            const float excl = x - i3;
            sc[j][0] = i0 + excl;
            sc[j][1] = i1 + excl;
            sc[j][2] = i2 + excl;
            sc[j][3] = i3 + excl;
            if (lane == 31) wsum[j][wid] = x;
        }
        __syncthreads();                           // wsum ready

        #pragma unroll
        for (int j = 0; j < 8; ++j) {
            float p = 0.f;
            #pragma unroll
            for (int t = 0; t < 2; ++t)
                if (t < wid) p += wsum[j][t];
            #pragma unroll
            for (int e = 0; e < 4; ++e) sc[j][e] += p;
        }

        // stage to smem: logical float4 q = 2e + h2 of thread t lives at
        // phys 8t + ((q+t)&7)  (bank-rotate kills STS conflicts)
        if (active) {
            #pragma unroll
            for (int e = 0; e < 4; ++e) {
                #pragma unroll
                for (int h2 = 0; h2 < 2; ++h2) {
                    const int q = 2 * e + h2;
                    xch[8 * slot + ((q + slot) & 7)] =
                        make_float4(sc[h2 * 4 + 0][e], sc[h2 * 4 + 1][e],
                                    sc[h2 * 4 + 2][e], sc[h2 * 4 + 3][e]);
                }
            }
        }
        __syncthreads();                           // xch ready

        // coalesced writeout of the whole 8704B row.
        // h advances by 1 -> float4 index advances by 32 octs * 2W = 64W.
        float4* gout = gout0 + (size_t)lh * (64 * W_);
        #pragma unroll
        for (int rr = 0; rr < 6; ++rr) {
            const int p = slot + 96 * rr;
            if (p < 544) {
                const int s = p >> 3, q = p & 7;
                gout[p] = xch[8 * s + ((q + s) & 7)];
            }
        }
        __syncthreads();                           // xch reusable next row
    }
}

// --------------------------------------------------------------------------
// carry[n][k][co][w][ci]: exclusive prefix over chunks of each chunk's
// last row. Linear thread index, ci fastest -> coalesced.
// --------------------------------------------------------------------------
__global__ void chunk_carry() {
    const int total = N_ * 32 * W_ * 8;
    int idx = blockIdx.x * 256 + threadIdx.x;
    if (idx >= total) return;
    const int ci = idx & 7;
    const int w  = (idx >> 3) % W_;
    const int co = ((idx >> 3) / W_) & 31;
    const int n  = idx / (8 * W_ * 32);

    float p = 0.f;
    #pragma unroll
    for (int k = 0; k < K_CH; ++k) {
        g_carry[((((size_t)(n * K_CH + k) * 32 + co) * W_ + w) << 3) + ci] = p;
        p += g_integ[((((size_t)(n * H_ + k * HCH + (HCH - 1)) * 32 + co) * W_ + w) << 3) + ci];
    }
}

// --------------------------------------------------------------------------
// Per-ROI gather. Block per ROI, 256 threads.
// Thread = (channel-quad cq = t&63, bin-group grp = t>>6);
// cq -> oct co = cq>>1, half h2 = cq&1; thread's channels = 4*cq..4*cq+3.
// --------------------------------------------------------------------------
__global__ void roipool(const int* __restrict__ rois, float* __restrict__ out,
                        int img_off, int R) {
    extern __shared__ float stage[];       // 256 * 49 floats
    __shared__ int sb[4 * O_];             // hs[7] he[7] ws[7] we[7]
    const int r = blockIdx.x;
    if (r >= R) return;
    const int t   = threadIdx.x;
    const int cq  = t & 63;
    const int grp = t >> 6;
    const int co  = cq >> 1;
    const int h2  = cq & 1;

    const int n  = rois[r * 5 + 0];
    const int x1 = rois[r * 5 + 1];
    const int y1 = rois[r * 5 + 2];
    const int x2 = rois[r * 5 + 3];
    const int y2 = rois[r * 5 + 4];

    if (t < O_) {
        const int hin = y2 - y1 + 1;
        const int win = x2 - x1 + 1;
        sb[t]          = y1 + (t * hin) / O_;                   // hs
        sb[O_ + t]     = y1 + ((t + 1) * hin + O_ - 1) / O_;    // he
        sb[2 * O_ + t] = x1 + (t * win) / O_;                   // ws
        sb[3 * O_ + t] = x1 + ((t + 1) * win + O_ - 1) / O_;    // we
    }
    __syncthreads();

    // float4 bases; per-h (or per-k) stride = 32 octs * 2W = 64W float4
    const float4* ib = (const float4*)g_integ
        + (size_t)n * ((size_t)H_ * 64 * W_) + (size_t)co * (2 * W_) + h2;
    const float4* cb = (const float4*)g_carry
        + (size_t)n * ((size_t)K_CH * 64 * W_) + (size_t)co * (2 * W_) + h2;
    const float4 z4 = make_float4(0.f, 0.f, 0.f, 0.f);

    if (img_off > 0 && t == 0) out[r] = (float)n;   // img_idx output

    #pragma unroll
    for (int m = 0; m < 13; ++m) {
        const int b = grp + 4 * m;
        if (b < O_ * O_) {
            const int i = b / O_;
            const int j = b - i * O_;
            const int hiT = sb[i];
            const int hiB = sb[O_ + i];
            const int wL  = sb[2 * O_ + j] - 1;   // may be -1 (pad)
            const int wR  = sb[3 * O_ + j] - 1;
            const int kB  = (hiB - 1) / HCH;
            const int kT  = (hiT > 0) ? (hiT - 1) / HCH : 0;

            // chunk-local integral corners
            float4 BR = ib[(size_t)(hiB - 1) * (64 * W_) + 2 * wR];
            float4 TR = (hiT > 0) ? ib[(size_t)(hiT - 1) * (64 * W_) + 2 * wR] : z4;
            float4 BL = (wL >= 0) ? ib[(size_t)(hiB - 1) * (64 * W_) + 2 * wL] : z4;
            float4 TL = (hiT > 0 && wL >= 0)
                      ? ib[(size_t)(hiT - 1) * (64 * W_) + 2 * wL] : z4;
            float4 s = f4sub(f4sub(BR, TR), f4sub(BL, TL));

            // carry correction; cancels when both rows in one chunk
            const bool need_carry = (hiT > 0) ? (kB != kT) : (kB != 0);
            if (need_carry) {
                float4 cR = cb[(size_t)kB * (64 * W_) + 2 * wR];
                if (hiT > 0) cR = f4sub(cR, cb[(size_t)kT * (64 * W_) + 2 * wR]);
                float4 cL = z4;
                if (wL >= 0) {
                    cL = cb[(size_t)kB * (64 * W_) + 2 * wL];
                    if (hiT > 0) cL = f4sub(cL, cb[(size_t)kT * (64 * W_) + 2 * wL]);
                }
                s = f4add(s, f4sub(cR, cL));
            }

            const float inv = 1.f / ((float)(hiB - hiT) *
                                     (float)(sb[3 * O_ + j] - sb[2 * O_ + j]));
            const int base = (4 * cq) * (O_ * O_) + b;
            stage[base]                 = s.x * inv;
            stage[base + O_ * O_]       = s.y * inv;
            stage[base + 2 * (O_ * O_)] = s.z * inv;
            stage[base + 3 * (O_ * O_)] = s.w * inv;
        }
    }
    __syncthreads();

    // coalesced float4 writeout of the whole tile
    float4* o4 = (float4*)(out + img_off + (size_t)r * (C_ * O_ * O_));
    const float4* s4 = (const float4*)stage;
    const int n4 = C_ * O_ * O_ / 4;   // 3136
    for (int p = t; p < n4; p += 256) o4[p] = s4[p];
}

// --------------------------------------------------------------------------
extern "C" void kernel_launch(void* const* d_in, const int* in_sizes, int n_in,
                              void* d_out, int out_size) {
    const float* fm   = (const float*)d_in[0];
    const int*   rois = (const int*)d_in[1];
    const int R = in_sizes[1] / 5;

    int img_off = out_size - R * C_ * O_ * O_;
    if (img_off < 0) img_off = 0;

    const int smem_bytes = C_ * O_ * O_ * (int)sizeof(float);   // 50176
    cudaFuncSetAttribute(roipool, cudaFuncAttributeMaxDynamicSharedMemorySize,
                         smem_bytes);

    dim3 gF(32, K_CH, N_);
    fused_scan<<<gF, 96>>>(fm);

    const int tot = N_ * C_ * W_;
    chunk_carry<<<(tot + 255) / 256, 256>>>();

    roipool<<<R, 256, smem_bytes>>>(rois, (float*)d_out, img_off, R);
}

// round 10
// speedup vs baseline: 1.5832x; 1.5832x over previous
#include <cuda_runtime.h>

#define N_ 4
#define C_ 256
#define H_ 200
#define W_ 272
#define O_ 7
#define K_CH 10         // h-chunks
#define HCH 20          // H_ / K_CH

// Integral image, 16-group-blocked TRANSPOSED layout:
//   g_integ[(((n*H + h)*16 + g)*W + w)*16 + ci]  with g=c>>4, ci=c&15.
// Per (n,h,g) the 272*16 floats are CONTIGUOUS (17KB) -> coalesced scan
// stores; per (h,w) a 64B piece per group -> 8-line corner reads in roipool.
__device__ float g_integ[(size_t)N_ * H_ * W_ * C_];
// carry, same layout: [n][k][g][w][ci]
__device__ float g_carry[(size_t)N_ * K_CH * W_ * C_];

__device__ __forceinline__ float4 f4add(float4 a, float4 b) {
    return make_float4(a.x + b.x, a.y + b.y, a.z + b.z, a.w + b.w);
}
__device__ __forceinline__ float4 f4sub(float4 a, float4 b) {
    return make_float4(a.x - b.x, a.y - b.y, a.z - b.z, a.w - b.w);
}

// --------------------------------------------------------------------------
// Fused H-scan + W-scan + transpose. Block: 160 threads (5 warps),
// thread = 2 consecutive w (136 active). Block owns (n, h-chunk k, c-group
// of 16). Stores staged through bank-rotated smem -> fully coalesced.
// Grid: (16, 10, 4) = 640 blocks.
// --------------------------------------------------------------------------
__global__ __launch_bounds__(160) void fused_scan(const float* __restrict__ fm) {
    __shared__ float  wsum[16][8];       // [channel][warp], 5 warps used
    __shared__ float4 xch[1088];         // one row: 272 w * 16 c = 1088 float4

    const int g  = blockIdx.x;           // c-group of 16
    const int c0 = g * 16;
    const int k  = blockIdx.y;
    const int n  = blockIdx.z;
    const int slot = threadIdx.x;        // 0..159, active < 136
    const int lane = slot & 31;
    const int wid  = slot >> 5;          // 0..4
    const bool active = (slot < 136);

    float accx[16], accy[16];
    #pragma unroll
    for (int j = 0; j < 16; ++j) { accx[j] = 0.f; accy[j] = 0.f; }

    const float2* in0 = (const float2*)(fm + ((size_t)(n * C_ + c0) * H_
                          + (size_t)k * HCH) * W_) + (active ? slot : 0);
    // float4 base of row h = k*HCH for this group
    float4* gout0 = (float4*)g_integ
        + ((size_t)((n * H_ + k * HCH) * 16 + g)) * (W_ * 4);

    for (int lh = 0; lh < HCH; ++lh) {
        float2 v[16];
        #pragma unroll
        for (int j = 0; j < 16; ++j)
            v[j] = in0[(size_t)j * (H_ * W_ / 2) + lh * (W_ / 2)];

        float s0[16], s1[16];
        #pragma unroll
        for (int j = 0; j < 16; ++j) {
            if (!active) { v[j].x = 0.f; v[j].y = 0.f; }
            accx[j] += v[j].x;
            accy[j] += v[j].y;
            const float i0 = accx[j];
            const float i1 = i0 + accy[j];
            float x = i1;                          // warp inclusive scan on totals
            #pragma unroll
            for (int d = 1; d < 32; d <<= 1) {
                float y = __shfl_up_sync(0xffffffff, x, d);
                if (lane >= d) x += y;
            }
            const float excl = x - i1;
            s0[j] = i0 + excl;
            s1[j] = i1 + excl;
            if (lane == 31) wsum[j][wid] = x;
        }
        __syncthreads();                           // wsum ready

        #pragma unroll
        for (int j = 0; j < 16; ++j) {
            float p = 0.f;
            #pragma unroll
            for (int t = 0; t < 4; ++t)
                if (t < wid) p += wsum[j][t];
            s0[j] += p;
            s1[j] += p;
        }

        // stage: logical float4 q = 4e + cq4 of thread lives at
        // phys 8*slot + ((q+slot)&7)  (bank-rotate kills STS conflicts)
        if (active) {
            #pragma unroll
            for (int e = 0; e < 2; ++e) {
                const float* sv = e ? s1 : s0;
                #pragma unroll
                for (int cq4 = 0; cq4 < 4; ++cq4) {
                    const int q = 4 * e + cq4;
                    xch[8 * slot + ((q + slot) & 7)] =
                        make_float4(sv[4 * cq4 + 0], sv[4 * cq4 + 1],
                                    sv[4 * cq4 + 2], sv[4 * cq4 + 3]);
                }
            }
        }
        __syncthreads();                           // xch ready

        // coalesced writeout of the 17408B row.
        // h advances by 1 -> float4 index advances by 16 groups * 4W = 64W.
        float4* gout = gout0 + (size_t)lh * (64 * W_);
        #pragma unroll
        for (int rr = 0; rr < 7; ++rr) {
            const int p = slot + 160 * rr;
            if (p < 1088) {
                const int s = p >> 3, q = p & 7;
                gout[p] = xch[8 * s + ((q + s) & 7)];
            }
        }
        __syncthreads();                           // xch reusable next row
    }
}

// --------------------------------------------------------------------------
// carry[n][k][g][w][ci]: exclusive prefix over chunks of each chunk's
// last row. Linear thread index, ci fastest -> coalesced.
// --------------------------------------------------------------------------
__global__ void chunk_carry() {
    const int total = N_ * 16 * W_ * 16;
    int idx = blockIdx.x * 256 + threadIdx.x;
    if (idx >= total) return;
    const int ci = idx & 15;
    const int w  = (idx >> 4) % W_;
    const int g  = ((idx >> 4) / W_) & 15;
    const int n  = idx / (16 * W_ * 16);

    float p = 0.f;
    #pragma unroll
    for (int k = 0; k < K_CH; ++k) {
        g_carry[((((size_t)(n * K_CH + k) * 16 + g) * W_ + w) << 4) + ci] = p;
        p += g_integ[((((size_t)(n * H_ + k * HCH + (HCH - 1)) * 16 + g) * W_ + w) << 4) + ci];
    }
}

// --------------------------------------------------------------------------
// Per-ROI gather. Block per ROI, 256 threads, TWO phases of 128 channels
// (halves smem staging to 25KB -> 8 blocks/SM -> single wave for R=1000).
// Phase thread = (local quad lq = t&31, bin-group grp = t>>5).
// Global quad cq = ph*32+lq -> group g = cq>>2, sub = cq&3; channels = 4*cq.
// --------------------------------------------------------------------------
__global__ void roipool(const int* __restrict__ rois, float* __restrict__ out,
                        int img_off, int R) {
    extern __shared__ float stage[];       // 128 * 49 floats = 25088 B
    __shared__ int sb[4 * O_];             // hs[7] he[7] ws[7] we[7]
    const int r = blockIdx.x;
    if (r >= R) return;
    const int t   = threadIdx.x;
    const int lq  = t & 31;
    const int grp = t >> 5;                // 0..7

    const int n  = rois[r * 5 + 0];
    const int x1 = rois[r * 5 + 1];
    const int y1 = rois[r * 5 + 2];
    const int x2 = rois[r * 5 + 3];
    const int y2 = rois[r * 5 + 4];

    if (t < O_) {
        const int hin = y2 - y1 + 1;
        const int win = x2 - x1 + 1;
        sb[t]          = y1 + (t * hin) / O_;                   // hs
        sb[O_ + t]     = y1 + ((t + 1) * hin + O_ - 1) / O_;    // he
        sb[2 * O_ + t] = x1 + (t * win) / O_;                   // ws
        sb[3 * O_ + t] = x1 + ((t + 1) * win + O_ - 1) / O_;    // we
    }
    __syncthreads();

    if (img_off > 0 && t == 0) out[r] = (float)n;   // img_idx output

    const float4 z4 = make_float4(0.f, 0.f, 0.f, 0.f);

    for (int ph = 0; ph < 2; ++ph) {
        const int cq  = ph * 32 + lq;
        const int gg  = cq >> 2;
        const int sub = cq & 3;

        // float4 bases; per-h (or per-k) stride = 16 groups * 4W = 64W float4
        const float4* ib = (const float4*)g_integ
            + (size_t)n * ((size_t)H_ * 64 * W_) + (size_t)gg * (4 * W_) + sub;
        const float4* cb = (const float4*)g_carry
            + (size_t)n * ((size_t)K_CH * 64 * W_) + (size_t)gg * (4 * W_) + sub;

        #pragma unroll
        for (int m = 0; m < 7; ++m) {
            const int b = grp + 8 * m;
            if (b < O_ * O_) {
                const int i = b / O_;
                const int j = b - i * O_;
                const int hiT = sb[i];
                const int hiB = sb[O_ + i];
                const int wL  = sb[2 * O_ + j] - 1;   // may be -1 (pad)
                const int wR  = sb[3 * O_ + j] - 1;
                const int kB  = (hiB - 1) / HCH;
                const int kT  = (hiT > 0) ? (hiT - 1) / HCH : 0;

                // chunk-local integral corners
                float4 BR = ib[(size_t)(hiB - 1) * (64 * W_) + 4 * wR];
                float4 TR = (hiT > 0) ? ib[(size_t)(hiT - 1) * (64 * W_) + 4 * wR] : z4;
                float4 BL = (wL >= 0) ? ib[(size_t)(hiB - 1) * (64 * W_) + 4 * wL] : z4;
                float4 TL = (hiT > 0 && wL >= 0)
                          ? ib[(size_t)(hiT - 1) * (64 * W_) + 4 * wL] : z4;
                float4 s = f4sub(f4sub(BR, TR), f4sub(BL, TL));

                // carry correction; cancels when both rows in one chunk
                const bool need_carry = (hiT > 0) ? (kB != kT) : (kB != 0);
                if (need_carry) {
                    float4 cR = cb[(size_t)kB * (64 * W_) + 4 * wR];
                    if (hiT > 0) cR = f4sub(cR, cb[(size_t)kT * (64 * W_) + 4 * wR]);
                    float4 cL = z4;
                    if (wL >= 0) {
                        cL = cb[(size_t)kB * (64 * W_) + 4 * wL];
                        if (hiT > 0) cL = f4sub(cL, cb[(size_t)kT * (64 * W_) + 4 * wL]);
                    }
                    s = f4add(s, f4sub(cR, cL));
                }

                const float inv = 1.f / ((float)(hiB - hiT) *
                                         (float)(sb[3 * O_ + j] - sb[2 * O_ + j]));
                const int base = (4 * lq) * (O_ * O_) + b;
                stage[base]                 = s.x * inv;
                stage[base + O_ * O_]       = s.y * inv;
                stage[base + 2 * (O_ * O_)] = s.z * inv;
                stage[base + 3 * (O_ * O_)] = s.w * inv;
            }
        }
        __syncthreads();

        // coalesced float4 writeout of this half (128 ch * 49 bins)
        float4* o4 = (float4*)(out + img_off + (size_t)r * (C_ * O_ * O_)
                               + (size_t)ph * (128 * O_ * O_));
        const float4* s4 = (const float4*)stage;
        const int n4 = 128 * O_ * O_ / 4;   // 1568
        for (int p = t; p < n4; p += 256) o4[p] = s4[p];
        __syncthreads();                    // stage reusable next phase
    }
}

// --------------------------------------------------------------------------
extern "C" void kernel_launch(void* const* d_in, const int* in_sizes, int n_in,
                              void* d_out, int out_size) {
    const float* fm   = (const float*)d_in[0];
    const int*   rois = (const int*)d_in[1];
    const int R = in_sizes[1] / 5;

    int img_off = out_size - R * C_ * O_ * O_;
    if (img_off < 0) img_off = 0;

    const int smem_bytes = 128 * O_ * O_ * (int)sizeof(float);   // 25088
    cudaFuncSetAttribute(roipool, cudaFuncAttributeMaxDynamicSharedMemorySize,
                         smem_bytes);

    dim3 gF(16, K_CH, N_);
    fused_scan<<<gF, 160>>>(fm);

    const int tot = N_ * C_ * W_;
    chunk_carry<<<(tot + 255) / 256, 256>>>();

    roipool<<<R, 256, smem_bytes>>>(rois, (float*)d_out, img_off, R);
}

// round 11
// speedup vs baseline: 1.6052x; 1.0139x over previous
#include <cuda_runtime.h>

#define N_ 4
#define C_ 256
#define H_ 200
#define W_ 272
#define O_ 7
#define K_CH 10         // h-chunks
#define HCH 20          // H_ / K_CH

// Integral image, 16-group-blocked TRANSPOSED layout:
//   g_integ[(((n*H + h)*16 + g)*W + w)*16 + ci]  with g=c>>4, ci=c&15.
__device__ float g_integ[(size_t)N_ * H_ * W_ * C_];
// carry, same layout: [n][k][g][w][ci]
__device__ float g_carry[(size_t)N_ * K_CH * W_ * C_];

__device__ __forceinline__ float4 f4add(float4 a, float4 b) {
    return make_float4(a.x + b.x, a.y + b.y, a.z + b.z, a.w + b.w);
}
__device__ __forceinline__ float4 f4sub(float4 a, float4 b) {
    return make_float4(a.x - b.x, a.y - b.y, a.z - b.z, a.w - b.w);
}

// --------------------------------------------------------------------------
// Fused H-scan + W-scan + transpose. Block: 320 threads = 2 warp-teams of 5
// warps; team hf handles channels [hf*8, hf*8+8) of the block's 16-channel
// group. Thread = 2 consecutive w (136 active per team). 8 ch/thread state
// -> ~68 regs -> 3 blocks/SM (30 warps). Contiguous 17KB row stores via
// bank-rotated smem staging. Grid: (16, 10, 4) = 640 blocks.
// --------------------------------------------------------------------------
__global__ __launch_bounds__(320, 3) void fused_scan(const float* __restrict__ fm) {
    __shared__ float  wsum[16][5];       // [channel][warp-in-team]
    __shared__ float4 xch[1088];         // one row: 272 w * 16 c = 1088 float4

    const int g  = blockIdx.x;           // c-group of 16
    const int c0 = g * 16;
    const int k  = blockIdx.y;
    const int n  = blockIdx.z;
    const int tid  = threadIdx.x;        // 0..319
    const int hf   = tid / 160;          // warp-team (warp-aligned: 160=5*32)
    const int s    = tid - hf * 160;     // slot in team, 0..159
    const int lane = s & 31;
    const int wih  = s >> 5;             // warp-in-team, 0..4
    const bool active = (s < 136);

    float accx[8], accy[8];
    #pragma unroll
    for (int j = 0; j < 8; ++j) { accx[j] = 0.f; accy[j] = 0.f; }

    const float2* in0 = (const float2*)(fm + ((size_t)(n * C_ + c0 + hf * 8) * H_
                          + (size_t)k * HCH) * W_) + (active ? s : 0);
    // float4 base of row h = k*HCH for this group
    float4* gout0 = (float4*)g_integ
        + ((size_t)((n * H_ + k * HCH) * 16 + g)) * (W_ * 4);

    for (int lh = 0; lh < HCH; ++lh) {
        float2 v[8];
        #pragma unroll
        for (int j = 0; j < 8; ++j)
            v[j] = in0[(size_t)j * (H_ * W_ / 2) + lh * (W_ / 2)];

        float s0[8], s1[8];
        #pragma unroll
        for (int j = 0; j < 8; ++j) {
            if (!active) { v[j].x = 0.f; v[j].y = 0.f; }
            accx[j] += v[j].x;
            accy[j] += v[j].y;
            const float i0 = accx[j];
            const float i1 = i0 + accy[j];
            float x = i1;                          // warp inclusive scan on totals
            #pragma unroll
            for (int d = 1; d < 32; d <<= 1) {
                float y = __shfl_up_sync(0xffffffff, x, d);
                if (lane >= d) x += y;
            }
            const float excl = x - i1;
            s0[j] = i0 + excl;
            s1[j] = i1 + excl;
            if (lane == 31) wsum[hf * 8 + j][wih] = x;
        }
        __syncthreads();                           // wsum ready

        #pragma unroll
        for (int j = 0; j < 8; ++j) {
            float p = 0.f;
            #pragma unroll
            for (int t = 0; t < 4; ++t)
                if (t < wih) p += wsum[hf * 8 + j][t];
            s0[j] += p;
            s1[j] += p;
        }

        // stage: logical float4 piece = 8s + off, off = 4e + 2*hf + quad2.
        // physical slot = 8s + ((off+s)&7)  (bank-rotate, conflict-free).
        if (active) {
            #pragma unroll
            for (int e = 0; e < 2; ++e) {
                const float* sv = e ? s1 : s0;
                #pragma unroll
                for (int q2 = 0; q2 < 2; ++q2) {
                    const int off = 4 * e + 2 * hf + q2;
                    xch[8 * s + ((off + s) & 7)] =
                        make_float4(sv[4 * q2 + 0], sv[4 * q2 + 1],
                                    sv[4 * q2 + 2], sv[4 * q2 + 3]);
                }
            }
        }
        __syncthreads();                           // xch ready

        // coalesced writeout of the 17408B row.
        // h advances by 1 -> float4 index advances by 16 groups * 4W = 64W.
        float4* gout = gout0 + (size_t)lh * (64 * W_);
        #pragma unroll
        for (int rr = 0; rr < 4; ++rr) {
            const int p = tid + 320 * rr;
            if (p < 1088) {
                const int ss = p >> 3, off = p & 7;
                gout[p] = xch[8 * ss + ((off + ss) & 7)];
            }
        }
        __syncthreads();                           // xch reusable next row
    }
}

// --------------------------------------------------------------------------
// carry[n][k][g][w][ci]: exclusive prefix over chunks of each chunk's
// last row. Linear thread index, ci fastest -> coalesced.
// --------------------------------------------------------------------------
__global__ void chunk_carry() {
    const int total = N_ * 16 * W_ * 16;
    int idx = blockIdx.x * 256 + threadIdx.x;
    if (idx >= total) return;
    const int ci = idx & 15;
    const int w  = (idx >> 4) % W_;
    const int g  = ((idx >> 4) / W_) & 15;
    const int n  = idx / (16 * W_ * 16);

    float p = 0.f;
    #pragma unroll
    for (int k = 0; k < K_CH; ++k) {
        g_carry[((((size_t)(n * K_CH + k) * 16 + g) * W_ + w) << 4) + ci] = p;
        p += g_integ[((((size_t)(n * H_ + k * HCH + (HCH - 1)) * 16 + g) * W_ + w) << 4) + ci];
    }
}

// --------------------------------------------------------------------------
// Per-ROI gather. Block per ROI, 256 threads, TWO phases of 128 channels
// (25KB smem staging -> 8 blocks/SM -> single wave for R=1000).
// Phase thread = (local quad lq = t&31, bin-group grp = t>>5).
// Global quad cq = ph*32+lq -> group g = cq>>2, sub = cq&3; channels = 4*cq.
// --------------------------------------------------------------------------
__global__ void roipool(const int* __restrict__ rois, float* __restrict__ out,
                        int img_off, int R) {
    extern __shared__ float stage[];       // 128 * 49 floats = 25088 B
    __shared__ int sb[4 * O_];             // hs[7] he[7] ws[7] we[7]
    const int r = blockIdx.x;
    if (r >= R) return;
    const int t   = threadIdx.x;
    const int lq  = t & 31;
    const int grp = t >> 5;                // 0..7

    const int n  = rois[r * 5 + 0];
    const int x1 = rois[r * 5 + 1];
    const int y1 = rois[r * 5 + 2];
    const int x2 = rois[r * 5 + 3];
    const int y2 = rois[r * 5 + 4];

    if (t < O_) {
        const int hin = y2 - y1 + 1;
        const int win = x2 - x1 + 1;
        sb[t]          = y1 + (t * hin) / O_;                   // hs
        sb[O_ + t]     = y1 + ((t + 1) * hin + O_ - 1) / O_;    // he
        sb[2 * O_ + t] = x1 + (t * win) / O_;                   // ws
        sb[3 * O_ + t] = x1 + ((t + 1) * win + O_ - 1) / O_;    // we
    }
    __syncthreads();

    if (img_off > 0 && t == 0) out[r] = (float)n;   // img_idx output

    const float4 z4 = make_float4(0.f, 0.f, 0.f, 0.f);

    for (int ph = 0; ph < 2; ++ph) {
        const int cq  = ph * 32 + lq;
        const int gg  = cq >> 2;
        const int sub = cq & 3;

        // float4 bases; per-h (or per-k) stride = 16 groups * 4W = 64W float4
        const float4* ib = (const float4*)g_integ
            + (size_t)n * ((size_t)H_ * 64 * W_) + (size_t)gg * (4 * W_) + sub;
        const float4* cb = (const float4*)g_carry
            + (size_t)n * ((size_t)K_CH * 64 * W_) + (size_t)gg * (4 * W_) + sub;

        #pragma unroll
        for (int m = 0; m < 7; ++m) {
            const int b = grp + 8 * m;
            if (b < O_ * O_) {
                const int i = b / O_;
                const int j = b - i * O_;
                const int hiT = sb[i];
                const int hiB = sb[O_ + i];
                const int wL  = sb[2 * O_ + j] - 1;   // may be -1 (pad)
                const int wR  = sb[3 * O_ + j] - 1;
                const int kB  = (hiB - 1) / HCH;
                const int kT  = (hiT > 0) ? (hiT - 1) / HCH : 0;

                // chunk-local integral corners
                float4 BR = ib[(size_t)(hiB - 1) * (64 * W_) + 4 * wR];
                float4 TR = (hiT > 0) ? ib[(size_t)(hiT - 1) * (64 * W_) + 4 * wR] : z4;
                float4 BL = (wL >= 0) ? ib[(size_t)(hiB - 1) * (64 * W_) + 4 * wL] : z4;
                float4 TL = (hiT > 0 && wL >= 0)
                          ? ib[(size_t)(hiT - 1) * (64 * W_) + 4 * wL] : z4;
                float4 s = f4sub(f4sub(BR, TR), f4sub(BL, TL));

                // carry correction; cancels when both rows in one chunk
                const bool need_carry = (hiT > 0) ? (kB != kT) : (kB != 0);
                if (need_carry) {
                    float4 cR = cb[(size_t)kB * (64 * W_) + 4 * wR];
                    if (hiT > 0) cR = f4sub(cR, cb[(size_t)kT * (64 * W_) + 4 * wR]);
                    float4 cL = z4;
                    if (wL >= 0) {
                        cL = cb[(size_t)kB * (64 * W_) + 4 * wL];
                        if (hiT > 0) cL = f4sub(cL, cb[(size_t)kT * (64 * W_) + 4 * wL]);
                    }
                    s = f4add(s, f4sub(cR, cL));
                }

                const float inv = 1.f / ((float)(hiB - hiT) *
                                         (float)(sb[3 * O_ + j] - sb[2 * O_ + j]));
                const int base = (4 * lq) * (O_ * O_) + b;
                stage[base]                 = s.x * inv;
                stage[base + O_ * O_]       = s.y * inv;
                stage[base + 2 * (O_ * O_)] = s.z * inv;
                stage[base + 3 * (O_ * O_)] = s.w * inv;
            }
        }
        __syncthreads();

        // coalesced float4 writeout of this half (128 ch * 49 bins)
        float4* o4 = (float4*)(out + img_off + (size_t)r * (C_ * O_ * O_)
                               + (size_t)ph * (128 * O_ * O_));
        const float4* s4 = (const float4*)stage;
        const int n4 = 128 * O_ * O_ / 4;   // 1568
        for (int p = t; p < n4; p += 256) o4[p] = s4[p];
        __syncthreads();                    // stage reusable next phase
    }
}

// --------------------------------------------------------------------------
extern "C" void kernel_launch(void* const* d_in, const int* in_sizes, int n_in,
                              void* d_out, int out_size) {
    const float* fm   = (const float*)d_in[0];
    const int*   rois = (const int*)d_in[1];
    const int R = in_sizes[1] / 5;

    int img_off = out_size - R * C_ * O_ * O_;
    if (img_off < 0) img_off = 0;

    const int smem_bytes = 128 * O_ * O_ * (int)sizeof(float);   // 25088
    cudaFuncSetAttribute(roipool, cudaFuncAttributeMaxDynamicSharedMemorySize,
                         smem_bytes);

    dim3 gF(16, K_CH, N_);
    fused_scan<<<gF, 320>>>(fm);

    const int tot = N_ * C_ * W_;
    chunk_carry<<<(tot + 255) / 256, 256>>>();

    roipool<<<R, 256, smem_bytes>>>(rois, (float*)d_out, img_off, R);
}